// round 7
// baseline (speedup 1.0000x reference)
#include <cuda_runtime.h>

// Resampling_79353815760907
// input_fmap: (B=16, P=4, H=32, W=32, D=32, C=8) float32
// theta:      (B=16, P=4, 3, 4) float32   out: (B,P,H,W,D,C) float32
//
// Round 6: h-walk plane reuse (round 5) + warp-uniform interior fast path.
//   interior point: x0,y0,z0 in [2,32] -> all 6 gather indices in-bounds,
//   no clamping, no weight zeroing. Tested with __all_sync per warp so the
//   branch is non-divergent. Fast path keeps a single plane pointer pA and
//   addresses all 8 corners with compile-time immediate offsets; non-fresh
//   steps cost just pA += 256 of integer work.
//   Slow path (volume edges) is the full round-5 body; it forces the next
//   step fresh so pA is never stale.
//
// Reference semantics preserved:
//   x = t00*w + t01*h + t02*d + t03 + 2  (rows 1,2 -> y,z)
//   x0 = clip(floor(x),0,34); x1 = x0+1 (not re-clipped)
//   gather padded[b,p, xi, yi, zi] (xi on H axis); orig = idx-2, zero OOB
//   xd = x - x0 (post-clip), trilinear blend.

__global__ void __launch_bounds__(256)
resample_kernel(const float* __restrict__ fmap,
                const float* __restrict__ theta,
                float* __restrict__ out) {
    const int g = blockIdx.x * 256 + threadIdx.x;
    const int half4 = (g & 1) << 2;   // 0: ch 0..3, 4: ch 4..7
    const int d   = (g >> 1) & 31;
    const int w   = (g >> 6) & 31;
    const int seg = (g >> 11) & 3;    // 8-step h segment
    const int bp  = g >> 13;          // b*P + p

    const float4* __restrict__ th4 = (const float4*)(theta + bp * 12);
    const float4 t0 = __ldg(th4 + 0);
    const float4 t1 = __ldg(th4 + 1);
    const float4 t2 = __ldg(th4 + 2);

    const float fw = (float)w, fd = (float)d;
    const float xb = fmaf(t0.x, fw, fmaf(t0.z, fd, t0.w)) + 2.0f;
    const float yb = fmaf(t1.x, fw, fmaf(t1.z, fd, t1.w)) + 2.0f;
    const float zb = fmaf(t2.x, fw, fmaf(t2.z, fd, t2.w)) + 2.0f;

    const float* __restrict__ base = fmap + bp * 262144 + half4;

    int h = seg << 3;
    float* __restrict__ optr =
        out + bp * 262144 + h * 8192 + w * 256 + (d << 3) + half4;

    int px0 = -100, py0 = -100, pz0 = -100;
    const float* pA = base;  // y0-plane base (valid only along fast chains)

    const float4 z4 = make_float4(0.f, 0.f, 0.f, 0.f);
    float4 A00 = z4, A01 = z4, A10 = z4, A11 = z4;
    float4 B00 = z4, B01 = z4, B10 = z4, B11 = z4;

    // P** = y0-plane slot (reused from prev step's y1), Q** = y1-plane slot
    auto step = [&](float4& P00, float4& P01, float4& P10, float4& P11,
                    float4& Q00, float4& Q01, float4& Q10, float4& Q11) {
        const float fh = (float)h;
        const float x = fmaf(t0.y, fh, xb);
        const float y = fmaf(t1.y, fh, yb);
        const float z = fmaf(t2.y, fh, zb);

        const int xi = __float2int_rd(x);
        const int yi = __float2int_rd(y);
        const int zi = __float2int_rd(z);

        // interior: all of x0,y0,z0 in [2,32] -> indices in-bounds, no clamp
        const bool interior = ((unsigned)(xi - 2) < 31u) &
                              ((unsigned)(yi - 2) < 31u) &
                              ((unsigned)(zi - 2) < 31u);

        float a00, a01, a10, a11, b00, b01, b10, b11;

        if (__all_sync(0xFFFFFFFFu, interior)) {
            // ---------- fast path (no clamp, no zeroing, imm offsets) ----------
            const bool fresh = (xi != px0) | (zi != pz0) | (yi != py0 + 1);
            px0 = xi; py0 = yi; pz0 = zi;

            if (fresh) {
                pA = base + ((xi - 2) << 13) + ((yi - 2) << 8) + ((zi - 2) << 3);
                P00 = __ldg((const float4*)(pA));
                P01 = __ldg((const float4*)(pA + 8));
                P10 = __ldg((const float4*)(pA + 8192));
                P11 = __ldg((const float4*)(pA + 8200));
            } else {
                pA += 256;
            }
            Q00 = __ldg((const float4*)(pA + 256));
            Q01 = __ldg((const float4*)(pA + 264));
            Q10 = __ldg((const float4*)(pA + 8448));
            Q11 = __ldg((const float4*)(pA + 8456));

            const float xd = x - (float)xi;
            const float yd = y - (float)yi;
            const float zd = z - (float)zi;
            const float wx0 = 1.f - xd, wx1 = xd;
            const float wy0 = 1.f - yd, wy1 = yd;
            const float wz0 = 1.f - zd, wz1 = zd;

            const float wxz00 = wx0 * wz0, wxz01 = wx0 * wz1;
            const float wxz10 = wx1 * wz0, wxz11 = wx1 * wz1;
            a00 = wxz00 * wy0; a01 = wxz01 * wy0;
            a10 = wxz10 * wy0; a11 = wxz11 * wy0;
            b00 = wxz00 * wy1; b01 = wxz01 * wy1;
            b10 = wxz10 * wy1; b11 = wxz11 * wy1;
        } else {
            // ---------- slow path (volume edges): full clamp/zero/wrap ----------
            const int x0 = min(max(xi, 0), 34);
            const int y0 = min(max(yi, 0), 34);
            const int z0 = min(max(zi, 0), 34);

            const float xd = x - (float)x0;
            const float yd = y - (float)y0;
            const float zd = z - (float)z0;

            float wx0 = 1.f - xd, wx1 = xd;
            float wy0 = 1.f - yd, wy1 = yd;
            float wz0 = 1.f - zd, wz1 = zd;
            if ((unsigned)(x0 - 2) >= 32u) wx0 = 0.f;
            if ((unsigned)(x0 - 1) >= 32u) wx1 = 0.f;
            if ((unsigned)(y0 - 2) >= 32u) wy0 = 0.f;
            if ((unsigned)(y0 - 1) >= 32u) wy1 = 0.f;
            if ((unsigned)(z0 - 2) >= 32u) wz0 = 0.f;
            if ((unsigned)(z0 - 1) >= 32u) wz1 = 0.f;

            const int HX0 = ((x0 - 2) & 31) << 13, HX1 = ((x0 - 1) & 31) << 13;
            const int WY0 = ((y0 - 2) & 31) << 8,  WY1 = ((y0 - 1) & 31) << 8;
            const int DZ0 = ((z0 - 2) & 31) << 3,  DZ1 = ((z0 - 1) & 31) << 3;

            P00 = __ldg((const float4*)(base + HX0 + WY0 + DZ0));
            P01 = __ldg((const float4*)(base + HX0 + WY0 + DZ1));
            P10 = __ldg((const float4*)(base + HX1 + WY0 + DZ0));
            P11 = __ldg((const float4*)(base + HX1 + WY0 + DZ1));
            Q00 = __ldg((const float4*)(base + HX0 + WY1 + DZ0));
            Q01 = __ldg((const float4*)(base + HX0 + WY1 + DZ1));
            Q10 = __ldg((const float4*)(base + HX1 + WY1 + DZ0));
            Q11 = __ldg((const float4*)(base + HX1 + WY1 + DZ1));

            const float wxz00 = wx0 * wz0, wxz01 = wx0 * wz1;
            const float wxz10 = wx1 * wz0, wxz11 = wx1 * wz1;
            a00 = wxz00 * wy0; a01 = wxz01 * wy0;
            a10 = wxz10 * wy0; a11 = wxz11 * wy0;
            b00 = wxz00 * wy1; b01 = wxz01 * wy1;
            b10 = wxz10 * wy1; b11 = wxz11 * wy1;

            px0 = -100;  // pA not maintained -> force fresh next step
        }

        // ---------- common blend + store ----------
        float4 acc;
        acc.x = a00 * P00.x; acc.y = a00 * P00.y;
        acc.z = a00 * P00.z; acc.w = a00 * P00.w;
        #define ACC(ww_, c)                                                  \
            acc.x = fmaf(ww_, c.x, acc.x); acc.y = fmaf(ww_, c.y, acc.y);    \
            acc.z = fmaf(ww_, c.z, acc.z); acc.w = fmaf(ww_, c.w, acc.w);
        ACC(a01, P01) ACC(a10, P10) ACC(a11, P11)
        ACC(b00, Q00) ACC(b01, Q01) ACC(b10, Q10) ACC(b11, Q11)
        #undef ACC

        *(float4*)optr = acc;
        optr += 8192;
        ++h;
    };

    #pragma unroll 1
    for (int it = 0; it < 4; ++it) {
        step(A00, A01, A10, A11, B00, B01, B10, B11);
        step(B00, B01, B10, B11, A00, A01, A10, A11);
    }
}

extern "C" void kernel_launch(void* const* d_in, const int* in_sizes, int n_in,
                              void* d_out, int out_size) {
    const float* fmap  = (const float*)d_in[0];
    const float* theta = (const float*)d_in[1];
    float* out = (float*)d_out;

    // threads = B*P * 4 segments * W * D * 2 halves = 524288
    const int blocks = 524288 / 256;   // 2048
    resample_kernel<<<blocks, 256>>>(fmap, theta, out);
}